// round 8
// baseline (speedup 1.0000x reference)
#include <cuda_runtime.h>
#include <cuda_bf16.h>
#include <cstdint>
#include <math.h>

#define B_      32
#define S_      2048
#define ENC_    1024
#define DEC_    512
#define WROW    1536
#define M_TOTAL 65536

#define BM 128
#define BN 128
#define KC 32
#define NSTAGE 32
#define NBUF 3
#define NTHREADS 256

// smem (from 1024-aligned base): vs 512B | hs 512B | red 2KB | tiles
#define OFF_VS    0
#define OFF_HS    512
#define OFF_RED   1024
#define OFF_TILES 4096
#define STAGE_BYTES 32768          // A 16K (hi|lo interleaved per row) + B 16K
#define SMEM_DYN (1024 + OFF_TILES + NBUF * STAGE_BYTES)   // 103424

__device__ __align__(256) __nv_bfloat16 g_we_hi[DEC_ * ENC_];
__device__ __align__(256) __nv_bfloat16 g_we_lo[DEC_ * ENC_];
__device__ __align__(256) __nv_bfloat16 g_a_hi[(size_t)M_TOTAL * ENC_];
__device__ __align__(256) __nv_bfloat16 g_a_lo[(size_t)M_TOTAL * ENC_];
__device__ float g_hproj[B_ * DEC_];
__device__ float g_partial[4 * M_TOTAL];

// ---------------- helpers ----------------
__device__ __forceinline__ uint32_t smem_u32(const void* p) {
    uint32_t a;
    asm("{ .reg .u64 t; cvta.to.shared.u64 t, %1; cvt.u32.u64 %0, t; }" : "=r"(a) : "l"(p));
    return a;
}
__device__ __forceinline__ uint32_t swz(uint32_t o) { return o ^ ((o >> 3) & 0x70); }
__device__ __forceinline__ void cp16(uint32_t dst, const void* src) {
    asm volatile("cp.async.cg.shared.global [%0], [%1], 16;"
                 :: "r"(dst), "l"(__cvta_generic_to_global(src)) : "memory");
}
__device__ __forceinline__ uint32_t pk(__nv_bfloat16 a, __nv_bfloat16 b) {
    __nv_bfloat162 p; p.x = a; p.y = b;
    return *reinterpret_cast<uint32_t*>(&p);
}
__device__ __forceinline__ float tanh_ffma(float x) {
    float xc = fminf(fmaxf(x, -8.f), 8.f);
    float y  = xc * 2.88539008177793f;
    float t  = y + 12582912.f;
    int   k  = __float_as_int(t) - __float_as_int(12582912.f);
    float f  = y - (t - 12582912.f);
    float p = 1.3333558146e-3f;
    p = fmaf(p, f, 9.6181291076e-3f);
    p = fmaf(p, f, 5.5504108664e-2f);
    p = fmaf(p, f, 2.4022650696e-1f);
    p = fmaf(p, f, 6.9314718056e-1f);
    p = fmaf(p, f, 1.0f);
    float E = __int_as_float(__float_as_int(p) + (k << 23));
    float D = E + 1.f;
    float r = __int_as_float(0x7EF311C3 - __float_as_int(D));
    r = r * fmaf(-D, r, 2.f);
    r = r * fmaf(-D, r, 2.f);
    r = r * fmaf(-D, r, 2.f);
    return fmaf(-2.f, r, 1.f);
}
__device__ __forceinline__ void ldsm4(uint32_t* r, uint32_t addr) {
    asm volatile("ldmatrix.sync.aligned.m8n8.x4.shared.b16 {%0,%1,%2,%3}, [%4];"
                 : "=r"(r[0]), "=r"(r[1]), "=r"(r[2]), "=r"(r[3]) : "r"(addr));
}
__device__ __forceinline__ void mma16816(float* c, const uint32_t* a, uint32_t b0, uint32_t b1) {
    asm volatile("mma.sync.aligned.m16n8k16.row.col.f32.bf16.bf16.f32 "
                 "{%0,%1,%2,%3}, {%4,%5,%6,%7}, {%8,%9}, {%0,%1,%2,%3};"
                 : "+f"(c[0]), "+f"(c[1]), "+f"(c[2]), "+f"(c[3])
                 : "r"(a[0]), "r"(a[1]), "r"(a[2]), "r"(a[3]), "r"(b0), "r"(b1));
}

// ---------------- kernel 0a: We -> bf16 hi/lo ----------------
__global__ void conv_we_kernel(const float* __restrict__ W) {
    const int d = blockIdx.x, t = threadIdx.x;
    float4 x = *reinterpret_cast<const float4*>(W + (size_t)d * WROW + DEC_ + t * 4);
    float e[4] = {x.x, x.y, x.z, x.w};
    __nv_bfloat16 h[4], l[4];
#pragma unroll
    for (int i = 0; i < 4; i++) {
        h[i] = __float2bfloat16(e[i]);
        l[i] = __float2bfloat16(e[i] - __bfloat162float(h[i]));
    }
    *reinterpret_cast<uint2*>(g_we_hi + d * ENC_ + t * 4) = make_uint2(pk(h[0],h[1]), pk(h[2],h[3]));
    *reinterpret_cast<uint2*>(g_we_lo + d * ENC_ + t * 4) = make_uint2(pk(l[0],l[1]), pk(l[2],l[3]));
}

// ---------------- kernel 0b: enc -> bf16 hi/lo ----------------
__global__ void conv_a_kernel(const float* __restrict__ enc) {
    size_t i = (size_t)blockIdx.x * blockDim.x + threadIdx.x;
    float4 x = reinterpret_cast<const float4*>(enc)[i];
    float e[4] = {x.x, x.y, x.z, x.w};
    __nv_bfloat16 h[4], l[4];
#pragma unroll
    for (int j = 0; j < 4; j++) {
        h[j] = __float2bfloat16(e[j]);
        l[j] = __float2bfloat16(e[j] - __bfloat162float(h[j]));
    }
    reinterpret_cast<uint2*>(g_a_hi)[i] = make_uint2(pk(h[0],h[1]), pk(h[2],h[3]));
    reinterpret_cast<uint2*>(g_a_lo)[i] = make_uint2(pk(l[0],l[1]), pk(l[2],l[3]));
}

// ---------------- kernel 1: hproj ----------------
__global__ void hproj_kernel(const float* __restrict__ hidden,
                             const float* __restrict__ W,
                             const float* __restrict__ bvec) {
    __shared__ float hid[DEC_];
    const int b = blockIdx.y;
    const int n = blockIdx.x * 128 + threadIdx.x;
    for (int i = threadIdx.x; i < DEC_; i += 128) hid[i] = hidden[b * DEC_ + i];
    __syncthreads();
    const float4* wr = reinterpret_cast<const float4*>(W + (size_t)n * WROW);
    float acc = bvec[n];
#pragma unroll 8
    for (int k = 0; k < DEC_ / 4; k++) {
        float4 w = wr[k];
        acc += hid[k*4]*w.x + hid[k*4+1]*w.y + hid[k*4+2]*w.z + hid[k*4+3]*w.w;
    }
    g_hproj[b * DEC_ + n] = acc;
}

// ---------------- kernel 2: HMMA GEMM, 2 CTA/SM, 3-stage pipeline ----------------
__global__ __launch_bounds__(NTHREADS, 2)
void gemm_kernel(const float* __restrict__ v) {
    extern __shared__ char sraw[];
    uint32_t sb0 = smem_u32(sraw);
    uint32_t sb = (sb0 + 1023u) & ~1023u;
    char* smem = sraw + (sb - sb0);

    const int tid  = threadIdx.x;
    const int lane = tid & 31;
    const int w    = tid >> 5;           // 0..7
    const int wm   = w >> 2;             // 0..1 (64 M rows)
    const int wn   = w & 3;              // 0..3 (32 N cols)
    const int g8   = lane >> 3;
    const int r8   = lane & 7;
    const int n0   = blockIdx.x * BN;
    const int m0   = blockIdx.y * BM;
    const int batch = m0 >> 11;

    float* vs = (float*)(smem + OFF_VS);
    float* hs = (float*)(smem + OFF_HS);
    if (tid < 128) {
        vs[tid] = v[n0 + tid];
        hs[tid] = g_hproj[batch * DEC_ + n0 + tid];
    }

    // ---- cp.async thread assignment (constant per thread) ----
    const int c7  = tid & 7;             // chunk: 0-3 hi, 4-7 lo
    const int sel = c7 >> 2;
    const int cc4 = c7 & 3;
    const int rb  = tid >> 3;            // 0..31
    const __nv_bfloat16* gA = (sel ? g_a_lo : g_a_hi) + (size_t)(m0 + rb) * ENC_ + cc4 * 8;
    const __nv_bfloat16* gB = (sel ? g_we_lo : g_we_hi) + (size_t)(n0 + rb) * ENC_ + cc4 * 8;
    uint32_t so[4];
#pragma unroll
    for (int i = 0; i < 4; i++)
        so[i] = swz((rb + i * 32) * 128 + sel * 64 + cc4 * 16);

    // ---- ldsm address bases (XOR-folded swizzle) ----
    const int a_row_sel = r8 + (g8 & 1) * 8;
    const int chunk16   = (g8 >> 1) * 16;
    uint32_t pA[4], pB[2];
#pragma unroll
    for (int mt = 0; mt < 4; mt++) {
        uint32_t R = (wm * 64 + mt * 16 + a_row_sel) * 128;
        pA[mt] = R + (chunk16 ^ ((R >> 3) & 0x70));
    }
#pragma unroll
    for (int ng = 0; ng < 2; ng++) {
        uint32_t R = (wn * 32 + ng * 16 + a_row_sel) * 128;
        pB[ng] = 16384 + R + (chunk16 ^ ((R >> 3) & 0x70));
    }

    // ---- prologue: stages 0,1 ----
#pragma unroll
    for (int s = 0; s < 2; s++) {
        uint32_t ab = sb + OFF_TILES + s * STAGE_BYTES;
#pragma unroll
        for (int i = 0; i < 4; i++) {
            cp16(ab + so[i],         gA + (size_t)i * 32 * ENC_ + s * KC);
            cp16(ab + 16384 + so[i], gB + (size_t)i * 32 * ENC_ + s * KC);
        }
        asm volatile("cp.async.commit_group;" ::: "memory");
    }

    float c[4][4][4];
#pragma unroll
    for (int mt = 0; mt < 4; mt++)
#pragma unroll
        for (int nt = 0; nt < 4; nt++)
#pragma unroll
            for (int q = 0; q < 4; q++) c[mt][nt][q] = 0.f;

    int buf = 0;
#pragma unroll 1
    for (int kt = 0; kt < NSTAGE; kt++) {
        if (kt < NSTAGE - 1) asm volatile("cp.async.wait_group 1;" ::: "memory");
        else                 asm volatile("cp.async.wait_group 0;" ::: "memory");
        __syncthreads();

        // issue stage kt+2
        if (kt + 2 < NSTAGE) {
            int nb = buf + 2; if (nb >= NBUF) nb -= NBUF;
            uint32_t ab = sb + OFF_TILES + nb * STAGE_BYTES;
            const int kb = (kt + 2) * KC;
#pragma unroll
            for (int i = 0; i < 4; i++) {
                cp16(ab + so[i],         gA + (size_t)i * 32 * ENC_ + kb);
                cp16(ab + 16384 + so[i], gB + (size_t)i * 32 * ENC_ + kb);
            }
            asm volatile("cp.async.commit_group;" ::: "memory");
        }

        // compute stage kt
        const uint32_t tb = sb + OFF_TILES + buf * STAGE_BYTES;
#pragma unroll
        for (int k16 = 0; k16 < 2; k16++) {
            const uint32_t kx = k16 << 5;
            uint32_t bhf[2][4], blf[2][4];
#pragma unroll
            for (int ng = 0; ng < 2; ng++) {
                uint32_t ad = (tb + pB[ng]) ^ kx;
                ldsm4(bhf[ng], ad);
                ldsm4(blf[ng], ad ^ 64);
            }
#pragma unroll
            for (int mt = 0; mt < 4; mt++) {
                uint32_t aa = (tb + pA[mt]) ^ kx;
                uint32_t ahf[4], alf[4];
                ldsm4(ahf, aa);
                ldsm4(alf, aa ^ 64);
#pragma unroll
                for (int ng = 0; ng < 2; ng++)
#pragma unroll
                    for (int s = 0; s < 2; s++) {
                        float* cc = c[mt][ng * 2 + s];
                        mma16816(cc, ahf, bhf[ng][s], bhf[ng][s + 2]);
                        mma16816(cc, ahf, blf[ng][s], blf[ng][s + 2]);
                        mma16816(cc, alf, bhf[ng][s], bhf[ng][s + 2]);
                    }
            }
        }
        if (++buf == NBUF) buf = 0;
    }

    // ---- fused epilogue ----
    const int g = lane >> 2, q = lane & 3;
    float* red = (float*)(smem + OFF_RED);
    __syncthreads();
#pragma unroll
    for (int mt = 0; mt < 4; mt++) {
        float r0 = 0.f, r1 = 0.f;
#pragma unroll
        for (int nt = 0; nt < 4; nt++) {
            int n = wn * 32 + nt * 8 + q * 2;
            float v0 = vs[n], v1 = vs[n + 1], h0 = hs[n], h1 = hs[n + 1];
            r0 += v0 * tanh_ffma(c[mt][nt][0] + h0) + v1 * tanh_ffma(c[mt][nt][1] + h1);
            r1 += v0 * tanh_ffma(c[mt][nt][2] + h0) + v1 * tanh_ffma(c[mt][nt][3] + h1);
        }
#pragma unroll
        for (int msk = 1; msk <= 2; msk <<= 1) {
            r0 += __shfl_xor_sync(0xffffffff, r0, msk);
            r1 += __shfl_xor_sync(0xffffffff, r1, msk);
        }
        if (q == 0) {
            int row = wm * 64 + mt * 16 + g;
            red[row * 4 + wn] = r0;
            red[(row + 8) * 4 + wn] = r1;
        }
    }
    __syncthreads();
    if (tid < 128)
        g_partial[(size_t)blockIdx.x * M_TOTAL + m0 + tid] =
            red[tid * 4] + red[tid * 4 + 1] + red[tid * 4 + 2] + red[tid * 4 + 3];
}

// ---------------- kernel 3: softmax ----------------
__global__ void softmax_kernel(float* __restrict__ out) {
    __shared__ float sc[S_];
    __shared__ float rb[256];
    const int b = blockIdx.x, tid = threadIdx.x;
    float lmax = -1e30f;
    for (int s = tid; s < S_; s += 256) {
        float x = g_partial[b * S_ + s] + g_partial[M_TOTAL + b * S_ + s]
                + g_partial[2 * M_TOTAL + b * S_ + s] + g_partial[3 * M_TOTAL + b * S_ + s];
        sc[s] = x;
        lmax = fmaxf(lmax, x);
    }
    rb[tid] = lmax; __syncthreads();
    for (int o = 128; o > 0; o >>= 1) {
        if (tid < o) rb[tid] = fmaxf(rb[tid], rb[tid + o]);
        __syncthreads();
    }
    const float m = rb[0]; __syncthreads();
    float ls = 0.f;
    for (int s = tid; s < S_; s += 256) {
        float e = __expf(sc[s] - m);
        sc[s] = e; ls += e;
    }
    rb[tid] = ls; __syncthreads();
    for (int o = 128; o > 0; o >>= 1) {
        if (tid < o) rb[tid] += rb[tid + o];
        __syncthreads();
    }
    const float inv = 1.f / rb[0]; __syncthreads();
    for (int s = tid; s < S_; s += 256)
        out[b * S_ + s] = sc[s] * inv;
}

// ---------------- launcher ----------------
extern "C" void kernel_launch(void* const* d_in, const int* in_sizes, int n_in,
                              void* d_out, int out_size) {
    const float* hidden = (const float*)d_in[0];
    const float* enc    = (const float*)d_in[1];
    const float* W      = (const float*)d_in[2];
    const float* bvec   = (const float*)d_in[3];
    const float* v      = (const float*)d_in[4];
    float* out          = (float*)d_out;

    cudaFuncSetAttribute(gemm_kernel, cudaFuncAttributeMaxDynamicSharedMemorySize, SMEM_DYN);

    conv_we_kernel<<<DEC_, 256>>>(W);
    conv_a_kernel<<<(size_t)M_TOTAL * ENC_ / 4 / 256, 256>>>(enc);
    hproj_kernel<<<dim3(4, B_), 128>>>(hidden, W, bvec);
    gemm_kernel<<<dim3(DEC_ / BN, M_TOTAL / BM), NTHREADS, SMEM_DYN>>>(v);
    softmax_kernel<<<B_, 256>>>(out);
}

// round 9
// speedup vs baseline: 1.0523x; 1.0523x over previous
#include <cuda_runtime.h>
#include <cuda_bf16.h>
#include <cstdint>
#include <math.h>

#define B_      32
#define S_      2048
#define ENC_    1024
#define DEC_    512
#define WROW    1536
#define M_TOTAL 65536

#define BM 128
#define BN 256
#define KC 64
#define NSTAGE 16
#define NTHREADS 512

// dynamic smem layout (from 1024-aligned base)
#define OFF_VS    0
#define OFF_HS    1024
#define OFF_RED   2048
#define OFF_TILES 4096
#define STAGE_BYTES 98304        // Ahi 16K + Alo 16K + Bhi 32K + Blo 32K
#define AHI_OFF(s) (OFF_TILES + (s) * STAGE_BYTES)
#define ALO_OFF(s) (AHI_OFF(s) + 16384)
#define BHI_OFF(s) (AHI_OFF(s) + 32768)
#define BLO_OFF(s) (AHI_OFF(s) + 65536)
#define SMEM_DYN (1024 + OFF_TILES + 2 * STAGE_BYTES)   // 201728

__device__ __align__(256) __nv_bfloat16 g_we_hi[DEC_ * ENC_];
__device__ __align__(256) __nv_bfloat16 g_we_lo[DEC_ * ENC_];
__device__ __align__(256) __nv_bfloat16 g_a_hi[(size_t)M_TOTAL * ENC_];
__device__ __align__(256) __nv_bfloat16 g_a_lo[(size_t)M_TOTAL * ENC_];
__device__ float g_hproj[B_ * DEC_];
__device__ float g_partial[2 * M_TOTAL];

// ---------------- helpers ----------------
__device__ __forceinline__ uint32_t smem_u32(const void* p) {
    uint32_t a;
    asm("{ .reg .u64 t; cvta.to.shared.u64 t, %1; cvt.u32.u64 %0, t; }" : "=r"(a) : "l"(p));
    return a;
}
__device__ __forceinline__ uint32_t swz(uint32_t o) { return o ^ ((o >> 3) & 0x70); }
__device__ __forceinline__ void cp16(uint32_t dst, const void* src) {
    asm volatile("cp.async.cg.shared.global [%0], [%1], 16;"
                 :: "r"(dst), "l"(__cvta_generic_to_global(src)) : "memory");
}
__device__ __forceinline__ uint32_t pk(__nv_bfloat16 a, __nv_bfloat16 b) {
    __nv_bfloat162 p; p.x = a; p.y = b;
    return *reinterpret_cast<uint32_t*>(&p);
}
__device__ __forceinline__ float tanh_ffma(float x) {
    float xc = fminf(fmaxf(x, -8.f), 8.f);
    float y  = xc * 2.88539008177793f;
    float t  = y + 12582912.f;
    int   k  = __float_as_int(t) - __float_as_int(12582912.f);
    float f  = y - (t - 12582912.f);
    float p = 1.3333558146e-3f;
    p = fmaf(p, f, 9.6181291076e-3f);
    p = fmaf(p, f, 5.5504108664e-2f);
    p = fmaf(p, f, 2.4022650696e-1f);
    p = fmaf(p, f, 6.9314718056e-1f);
    p = fmaf(p, f, 1.0f);
    float E = __int_as_float(__float_as_int(p) + (k << 23));
    float D = E + 1.f;
    float r = __int_as_float(0x7EF311C3 - __float_as_int(D));
    r = r * fmaf(-D, r, 2.f);
    r = r * fmaf(-D, r, 2.f);
    r = r * fmaf(-D, r, 2.f);
    return fmaf(-2.f, r, 1.f);
}
__device__ __forceinline__ void ldsm4(uint32_t* r, uint32_t addr) {
    asm volatile("ldmatrix.sync.aligned.m8n8.x4.shared.b16 {%0,%1,%2,%3}, [%4];"
                 : "=r"(r[0]), "=r"(r[1]), "=r"(r[2]), "=r"(r[3]) : "r"(addr));
}
__device__ __forceinline__ void mma16816(float* c, const uint32_t* a, uint32_t b0, uint32_t b1) {
    asm volatile("mma.sync.aligned.m16n8k16.row.col.f32.bf16.bf16.f32 "
                 "{%0,%1,%2,%3}, {%4,%5,%6,%7}, {%8,%9}, {%0,%1,%2,%3};"
                 : "+f"(c[0]), "+f"(c[1]), "+f"(c[2]), "+f"(c[3])
                 : "r"(a[0]), "r"(a[1]), "r"(a[2]), "r"(a[3]), "r"(b0), "r"(b1));
}

// ---------------- kernel 0a: We -> bf16 hi/lo ----------------
__global__ void conv_we_kernel(const float* __restrict__ W) {
    const int d = blockIdx.x, t = threadIdx.x;
    float4 x = *reinterpret_cast<const float4*>(W + (size_t)d * WROW + DEC_ + t * 4);
    float e[4] = {x.x, x.y, x.z, x.w};
    __nv_bfloat16 h[4], l[4];
#pragma unroll
    for (int i = 0; i < 4; i++) {
        h[i] = __float2bfloat16(e[i]);
        l[i] = __float2bfloat16(e[i] - __bfloat162float(h[i]));
    }
    *reinterpret_cast<uint2*>(g_we_hi + d * ENC_ + t * 4) = make_uint2(pk(h[0],h[1]), pk(h[2],h[3]));
    *reinterpret_cast<uint2*>(g_we_lo + d * ENC_ + t * 4) = make_uint2(pk(l[0],l[1]), pk(l[2],l[3]));
}

// ---------------- kernel 0b: enc -> bf16 hi/lo ----------------
__global__ void conv_a_kernel(const float* __restrict__ enc) {
    size_t i = (size_t)blockIdx.x * blockDim.x + threadIdx.x;
    float4 x = reinterpret_cast<const float4*>(enc)[i];
    float e[4] = {x.x, x.y, x.z, x.w};
    __nv_bfloat16 h[4], l[4];
#pragma unroll
    for (int j = 0; j < 4; j++) {
        h[j] = __float2bfloat16(e[j]);
        l[j] = __float2bfloat16(e[j] - __bfloat162float(h[j]));
    }
    reinterpret_cast<uint2*>(g_a_hi)[i] = make_uint2(pk(h[0],h[1]), pk(h[2],h[3]));
    reinterpret_cast<uint2*>(g_a_lo)[i] = make_uint2(pk(l[0],l[1]), pk(l[2],l[3]));
}

// ---------------- kernel 1: hproj ----------------
__global__ void hproj_kernel(const float* __restrict__ hidden,
                             const float* __restrict__ W,
                             const float* __restrict__ bvec) {
    __shared__ float hid[DEC_];
    const int b = blockIdx.y;
    const int n = blockIdx.x * 128 + threadIdx.x;
    for (int i = threadIdx.x; i < DEC_; i += 128) hid[i] = hidden[b * DEC_ + i];
    __syncthreads();
    const float4* wr = reinterpret_cast<const float4*>(W + (size_t)n * WROW);
    float acc = bvec[n];
#pragma unroll 8
    for (int k = 0; k < DEC_ / 4; k++) {
        float4 w = wr[k];
        acc += hid[k*4]*w.x + hid[k*4+1]*w.y + hid[k*4+2]*w.z + hid[k*4+3]*w.w;
    }
    g_hproj[b * DEC_ + n] = acc;
}

// ---------------- kernel 2: HMMA GEMM + fused epilogue ----------------
__global__ __launch_bounds__(NTHREADS, 1)
void gemm_kernel(const float* __restrict__ v) {
    extern __shared__ char sraw[];
    uint32_t sb0 = smem_u32(sraw);
    uint32_t sb = (sb0 + 1023u) & ~1023u;
    char* smem = sraw + (sb - sb0);

    const int tid  = threadIdx.x;
    const int lane = tid & 31;
    const int w    = tid >> 5;          // 0..15
    const int wm   = w >> 2;            // 0..3  (M: 32 rows)
    const int wn   = w & 3;             // 0..3  (N: 64 cols)
    const int g8   = lane >> 3;
    const int r8   = lane & 7;
    const int n0   = blockIdx.x * BN;
    const int m0   = blockIdx.y * BM;
    const int batch = m0 >> 11;

    float* vs = (float*)(smem + OFF_VS);
    float* hs = (float*)(smem + OFF_HS);
    if (tid < 256) {
        vs[tid] = v[n0 + tid];
        hs[tid] = g_hproj[batch * DEC_ + n0 + tid];
    }

    // prologue: stage 0
    {
        uint32_t ah = sb + AHI_OFF(0), al = sb + ALO_OFF(0);
        uint32_t bh = sb + BHI_OFF(0), bl = sb + BLO_OFF(0);
#pragma unroll
        for (int i = 0; i < 2; i++) {
            int id = tid + i * NTHREADS;
            int row = id >> 3, c = id & 7;
            uint32_t so = swz(row * 128 + c * 16);
            size_t g = (size_t)(m0 + row) * ENC_ + c * 8;
            cp16(ah + so, g_a_hi + g);
            cp16(al + so, g_a_lo + g);
        }
#pragma unroll
        for (int i = 0; i < 4; i++) {
            int id = tid + i * NTHREADS;
            int row = id >> 3, c = id & 7;
            uint32_t so = swz(row * 128 + c * 16);
            size_t g = (size_t)(n0 + row) * ENC_ + c * 8;
            cp16(bh + so, g_we_hi + g);
            cp16(bl + so, g_we_lo + g);
        }
        asm volatile("cp.async.commit_group;" ::: "memory");
    }

    float c[2][8][4];
#pragma unroll
    for (int mt = 0; mt < 2; mt++)
#pragma unroll
        for (int nt = 0; nt < 8; nt++)
#pragma unroll
            for (int q = 0; q < 4; q++) c[mt][nt][q] = 0.f;

    const int a_row_sel = r8 + (g8 & 1) * 8;
    const int chunk16   = (g8 >> 1) * 16;

#pragma unroll 1
    for (int kt = 0; kt < NSTAGE; kt++) {
        const int b = kt & 1;
        asm volatile("cp.async.wait_group 0;" ::: "memory");
        __syncthreads();

        // issue loads for kt+1 (overlap with compute below)
        if (kt + 1 < NSTAGE) {
            const int nb = (kt + 1) & 1;
            const int kb = (kt + 1) * KC;
            uint32_t ah = sb + AHI_OFF(nb), al = sb + ALO_OFF(nb);
            uint32_t bh = sb + BHI_OFF(nb), bl = sb + BLO_OFF(nb);
#pragma unroll
            for (int i = 0; i < 2; i++) {
                int id = tid + i * NTHREADS;
                int row = id >> 3, cc = id & 7;
                uint32_t so = swz(row * 128 + cc * 16);
                size_t g = (size_t)(m0 + row) * ENC_ + kb + cc * 8;
                cp16(ah + so, g_a_hi + g);
                cp16(al + so, g_a_lo + g);
            }
#pragma unroll
            for (int i = 0; i < 4; i++) {
                int id = tid + i * NTHREADS;
                int row = id >> 3, cc = id & 7;
                uint32_t so = swz(row * 128 + cc * 16);
                size_t g = (size_t)(n0 + row) * ENC_ + kb + cc * 8;
                cp16(bh + so, g_we_hi + g);
                cp16(bl + so, g_we_lo + g);
            }
            asm volatile("cp.async.commit_group;" ::: "memory");
        }

        // compute stage kt: 4 k16 steps, 3 independent MMA sweeps each
        const uint32_t ahb = sb + AHI_OFF(b), alb = sb + ALO_OFF(b);
        const uint32_t bhb = sb + BHI_OFF(b), blb = sb + BLO_OFF(b);
#pragma unroll
        for (int k16 = 0; k16 < 4; k16++) {
            const uint32_t kby = k16 * 32 + chunk16;
            uint32_t ah[2][4], al[2][4], bh[4][4], bl[4][4];
#pragma unroll
            for (int mt = 0; mt < 2; mt++) {
                uint32_t ro = swz((wm * 32 + mt * 16 + a_row_sel) * 128 + kby);
                ldsm4(ah[mt], ahb + ro);
                ldsm4(al[mt], alb + ro);
            }
#pragma unroll
            for (int ng = 0; ng < 4; ng++) {
                uint32_t ro = swz((wn * 64 + ng * 16 + a_row_sel) * 128 + kby);
                ldsm4(bh[ng], bhb + ro);
                ldsm4(bl[ng], blb + ro);
            }
            // sweep 1: hi*hi — 16 independent accumulators
#pragma unroll
            for (int mt = 0; mt < 2; mt++)
#pragma unroll
                for (int ng = 0; ng < 4; ng++)
#pragma unroll
                    for (int s = 0; s < 2; s++)
                        mma16816(c[mt][ng * 2 + s], ah[mt], bh[ng][s], bh[ng][s + 2]);
            // sweep 2: hi*lo
#pragma unroll
            for (int mt = 0; mt < 2; mt++)
#pragma unroll
                for (int ng = 0; ng < 4; ng++)
#pragma unroll
                    for (int s = 0; s < 2; s++)
                        mma16816(c[mt][ng * 2 + s], ah[mt], bl[ng][s], bl[ng][s + 2]);
            // sweep 3: lo*hi
#pragma unroll
            for (int mt = 0; mt < 2; mt++)
#pragma unroll
                for (int ng = 0; ng < 4; ng++)
#pragma unroll
                    for (int s = 0; s < 2; s++)
                        mma16816(c[mt][ng * 2 + s], al[mt], bh[ng][s], bh[ng][s + 2]);
        }
        __syncthreads();
    }

    // ---- fused epilogue: v . tanh(C + h) ----
    const int g = lane >> 2, q = lane & 3;
    float* red = (float*)(smem + OFF_RED);
#pragma unroll
    for (int mt = 0; mt < 2; mt++) {
        float r0 = 0.f, r1 = 0.f;
#pragma unroll
        for (int nt = 0; nt < 8; nt++) {
            int n = wn * 64 + nt * 8 + q * 2;
            float v0 = vs[n], v1 = vs[n + 1], h0 = hs[n], h1 = hs[n + 1];
            r0 += v0 * tanh_ffma(c[mt][nt][0] + h0) + v1 * tanh_ffma(c[mt][nt][1] + h1);
            r1 += v0 * tanh_ffma(c[mt][nt][2] + h0) + v1 * tanh_ffma(c[mt][nt][3] + h1);
        }
#pragma unroll
        for (int msk = 1; msk <= 2; msk <<= 1) {
            r0 += __shfl_xor_sync(0xffffffff, r0, msk);
            r1 += __shfl_xor_sync(0xffffffff, r1, msk);
        }
        if (q == 0) {
            int row = wm * 32 + mt * 16 + g;
            red[row * 4 + wn] = r0;
            red[(row + 8) * 4 + wn] = r1;
        }
    }
    __syncthreads();
    if (tid < 128)
        g_partial[(size_t)blockIdx.x * M_TOTAL + m0 + tid] =
            red[tid * 4] + red[tid * 4 + 1] + red[tid * 4 + 2] + red[tid * 4 + 3];
}

// ---------------- kernel 3: softmax ----------------
__global__ void softmax_kernel(float* __restrict__ out) {
    __shared__ float sc[S_];
    __shared__ float rb[256];
    const int b = blockIdx.x, tid = threadIdx.x;
    float lmax = -1e30f;
    for (int s = tid; s < S_; s += 256) {
        float x = g_partial[b * S_ + s] + g_partial[M_TOTAL + b * S_ + s];
        sc[s] = x;
        lmax = fmaxf(lmax, x);
    }
    rb[tid] = lmax; __syncthreads();
    for (int o = 128; o > 0; o >>= 1) {
        if (tid < o) rb[tid] = fmaxf(rb[tid], rb[tid + o]);
        __syncthreads();
    }
    const float m = rb[0]; __syncthreads();
    float ls = 0.f;
    for (int s = tid; s < S_; s += 256) {
        float e = __expf(sc[s] - m);
        sc[s] = e; ls += e;
    }
    rb[tid] = ls; __syncthreads();
    for (int o = 128; o > 0; o >>= 1) {
        if (tid < o) rb[tid] += rb[tid + o];
        __syncthreads();
    }
    const float inv = 1.f / rb[0]; __syncthreads();
    for (int s = tid; s < S_; s += 256)
        out[b * S_ + s] = sc[s] * inv;
}

// ---------------- launcher ----------------
extern "C" void kernel_launch(void* const* d_in, const int* in_sizes, int n_in,
                              void* d_out, int out_size) {
    const float* hidden = (const float*)d_in[0];
    const float* enc    = (const float*)d_in[1];
    const float* W      = (const float*)d_in[2];
    const float* bvec   = (const float*)d_in[3];
    const float* v      = (const float*)d_in[4];
    float* out          = (float*)d_out;

    cudaFuncSetAttribute(gemm_kernel, cudaFuncAttributeMaxDynamicSharedMemorySize, SMEM_DYN);

    conv_we_kernel<<<DEC_, 256>>>(W);
    conv_a_kernel<<<(size_t)M_TOTAL * ENC_ / 4 / 256, 256>>>(enc);
    hproj_kernel<<<dim3(4, B_), 128>>>(hidden, W, bvec);
    gemm_kernel<<<dim3(DEC_ / BN, M_TOTAL / BM), NTHREADS, SMEM_DYN>>>(v);
    softmax_kernel<<<B_, 256>>>(out);
}